// round 5
// baseline (speedup 1.0000x reference)
#include <cuda_runtime.h>
#include <cstdint>

#define T_STEPS 8640
#define HID     128
#define BATCH   16
#define CSZ     8
#define SLICE   16          /* HID / CSZ */
#define NTH     384
#define LOG2E   1.4426950408889634f
#define H0_TX   512         /* 8 src * 64 B bulk */
#define H1_TX   544         /* 8 src * (64 B bulk + 4 B fc scalar) */

// ---------------- PTX helpers ----------------
__device__ __forceinline__ uint32_t smem_u32(const void* p) {
    return (uint32_t)__cvta_generic_to_shared(p);
}
__device__ __forceinline__ uint32_t mapa_rank(uint32_t a, uint32_t r) {
    uint32_t d;
    asm volatile("mapa.shared::cluster.u32 %0, %1, %2;" : "=r"(d) : "r"(a), "r"(r));
    return d;
}
// one bulk DSMEM copy = ONE tx event on the remote barrier (vs 8 for st.async scatter)
__device__ __forceinline__ void bulk_dsmem(uint32_t dst, uint32_t src,
                                           uint32_t bytes, uint32_t mb) {
    asm volatile(
        "cp.async.bulk.shared::cluster.shared::cta.mbarrier::complete_tx::bytes "
        "[%0], [%1], %2, [%3];"
        :: "r"(dst), "r"(src), "r"(bytes), "r"(mb) : "memory");
}
__device__ __forceinline__ void st_async32(uint32_t a, uint32_t v, uint32_t mb) {
    asm volatile("st.async.shared::cluster.mbarrier::complete_tx::bytes.b32 [%0], %1, [%2];"
                 :: "r"(a), "r"(v), "r"(mb) : "memory");
}
__device__ __forceinline__ void fence_async_proxy() {
    asm volatile("fence.proxy.async.shared::cta;" ::: "memory");
}
__device__ __forceinline__ void mb_init(uint32_t a, uint32_t n) {
    asm volatile("mbarrier.init.shared.b64 [%0], %1;" :: "r"(a), "r"(n) : "memory");
}
__device__ __forceinline__ void mb_expect(uint32_t a, uint32_t tx) {
    asm volatile("mbarrier.arrive.expect_tx.shared.b64 _, [%0], %1;"
                 :: "r"(a), "r"(tx) : "memory");
}
// cta-scope acquire wait: sufficient because data arrives via complete_tx
__device__ __forceinline__ void mb_wait(uint32_t a, uint32_t par) {
    asm volatile(
        "{\n\t"
        ".reg .pred P;\n\t"
        "WL_%=:\n\t"
        "mbarrier.try_wait.parity.acquire.cta.shared::cta.b64 P, [%0], %1, 0x989680;\n\t"
        "@P bra.uni WD_%=;\n\t"
        "bra.uni WL_%=;\n\t"
        "WD_%=:\n\t"
        "}"
        :: "r"(a), "r"(par) : "memory");
}
__device__ __forceinline__ void barn(int id, int n) {
    asm volatile("bar.sync %0, %1;" :: "r"(id), "r"(n) : "memory");
}
// fast transcendentals (~1e-6 rel err)
__device__ __forceinline__ float ex2f(float x) {
    float r; asm("ex2.approx.f32 %0, %1;" : "=f"(r) : "f"(x)); return r;
}
__device__ __forceinline__ float rcpf(float x) {
    float r; asm("rcp.approx.f32 %0, %1;" : "=f"(r) : "f"(x)); return r;
}
__device__ __forceinline__ float sigf(float x) {
    return rcpf(1.0f + ex2f(-LOG2E * x));
}
__device__ __forceinline__ float tanh_f(float x) {
    float t = ex2f(-2.0f * LOG2E * x);
    return (1.0f - t) * rcpf(1.0f + t);
}

#define DOT64(res, w, hv)                                            \
    {                                                                \
        float a0 = 0.f, a1 = 0.f, a2 = 0.f, a3 = 0.f;                \
        _Pragma("unroll")                                            \
        for (int k = 0; k < 16; k++) {                               \
            float4 v = (hv)[k];                                      \
            a0 = fmaf((w)[4 * k + 0], v.x, a0);                      \
            a1 = fmaf((w)[4 * k + 1], v.y, a1);                      \
            a2 = fmaf((w)[4 * k + 2], v.z, a2);                      \
            a3 = fmaf((w)[4 * k + 3], v.w, a3);                      \
        }                                                            \
        res = (a0 + a1) + (a2 + a3);                                 \
    }

// ---------------- kernel ----------------
// 8-CTA cluster per batch element; CTA `rank` owns hidden slice
// [16*rank, 16*rank+16) of both layers -> 64 gate rows of each matrix.
// Warp roles (hi-wid-first arbiter: critical warps get high wid):
//   warps 0-3  (grp 0): Whh1 rows (reads s_h1[p], off critical path)
//   warps 4-7  (grp 1): Whh0 rows, precomputed after syncthreads;
//                       warp 7 = layer-0 nonlin + h0 bulk broadcast
//   warps 8-11 (grp 2): Wih1 rows (critical dot);
//                       warp 11 = layer-1 nonlin + h1 bulk / fc st.async broadcast
__global__ void __launch_bounds__(NTH, 1) __cluster_dims__(CSZ, 1, 1)
lstm_decoder_kernel(
    const float* __restrict__ y0,
    const float* __restrict__ h0in,
    const float* __restrict__ c0in,
    const float* __restrict__ wih0,
    const float* __restrict__ whh0,
    const float* __restrict__ bih0,
    const float* __restrict__ bhh0,
    const float* __restrict__ wih1,
    const float* __restrict__ whh1,
    const float* __restrict__ bih1,
    const float* __restrict__ bhh1,
    const float* __restrict__ fcw,
    const float* __restrict__ fcb,
    float* __restrict__ out)
{
    __shared__ __align__(16) float s_h0[2][HID];
    __shared__ __align__(16) float s_h1[2][HID];
    __shared__ __align__(16) float s_g0[64];     // layer-0 pre-acts (grp1)
    __shared__ __align__(16) float s_g1a[64];    // bias + Whh1*h1    (grp0)
    __shared__ __align__(16) float s_g1b[64];    // Wih1*h0_new       (grp2)
    __shared__ __align__(16) float s_h0st[SLICE];
    __shared__ __align__(16) float s_h1st[SLICE];
    __shared__ __align__(16) float s_fcp[2][CSZ];
    __shared__ __align__(8) unsigned long long s_mb_h0[2];
    __shared__ __align__(8) unsigned long long s_mb_h1[2];

    const int tid  = threadIdx.x;
    const int lane = tid & 31;
    const int wid  = tid >> 5;
    uint32_t rank;
    asm("mov.u32 %0, %%cluster_ctarank;" : "=r"(rank));
    const int b = blockIdx.x >> 3;

    const int grp  = tid >> 7;               // 0:Whh1  1:Whh0  2:Wih1
    const int half = tid & 1;
    const int row  = (tid & 127) >> 1;       // local gate row 0..63
    const int gate = row >> 4;
    const int jloc = row & 15;
    const int grow = gate * HID + (int)rank * SLICE + jloc;

    const uint32_t a_mbh0_0 = smem_u32(&s_mb_h0[0]);
    const uint32_t a_mbh0_1 = smem_u32(&s_mb_h0[1]);
    const uint32_t a_mbh1_0 = smem_u32(&s_mb_h1[0]);
    const uint32_t a_mbh1_1 = smem_u32(&s_mb_h1[1]);

    if (tid == 0) {
        mb_init(a_mbh0_0, 1);
        mb_init(a_mbh0_1, 1);
        mb_init(a_mbh1_0, 1);
        mb_init(a_mbh1_1, 1);
        mb_expect(a_mbh0_0, H0_TX);
        mb_expect(a_mbh0_1, H0_TX);
        mb_expect(a_mbh1_0, H1_TX);
        mb_expect(a_mbh1_1, H1_TX);
        s_fcp[0][0] = y0[b] - fcb[0];        // stage so iter 0 sees y = y0[b]
        #pragma unroll
        for (int i = 1; i < CSZ; i++) s_fcp[0][i] = 0.0f;
    }

    for (int k = tid; k < HID; k += NTH) {
        s_h0[0][k] = h0in[b * HID + k];
        s_h1[0][k] = h0in[BATCH * HID + b * HID + k];
    }

    // weights (register-resident, 64 per thread)
    float w[64];
    {
        const float* Wsrc = (grp == 0) ? whh1 : (grp == 1) ? whh0 : wih1;
        const float* src  = Wsrc + (size_t)grow * HID + half * 64;
        #pragma unroll
        for (int i = 0; i < 64; i++) w[i] = src[i];
    }
    float bias = 0.0f, wi = 0.0f;
    if (half == 0) {
        if (grp == 0)      { bias = bih1[grow] + bhh1[grow]; }
        else if (grp == 1) { bias = bih0[grow] + bhh0[grow]; wi = wih0[grow]; }
    }

    float c0r = 0.0f, c1r = 0.0f, fcwr = 0.0f;
    if (wid == 7 && lane < SLICE)
        c0r = c0in[b * HID + (int)rank * SLICE + lane];
    if (wid == 11 && lane < SLICE) {
        c1r  = c0in[BATCH * HID + b * HID + (int)rank * SLICE + lane];
        fcwr = fcw[(int)rank * SLICE + lane];
    }
    const float fc_b = fcb[0];

    const uint32_t a_h0d_0 = smem_u32(&s_h0[0][(int)rank * SLICE]);
    const uint32_t a_h0d_1 = smem_u32(&s_h0[1][(int)rank * SLICE]);
    const uint32_t a_h1d_0 = smem_u32(&s_h1[0][(int)rank * SLICE]);
    const uint32_t a_h1d_1 = smem_u32(&s_h1[1][(int)rank * SLICE]);
    const uint32_t a_fcd_0 = smem_u32(&s_fcp[0][rank]);
    const uint32_t a_fcd_1 = smem_u32(&s_fcp[1][rank]);
    const uint32_t a_h0st  = smem_u32(s_h0st);
    const uint32_t a_h1st  = smem_u32(s_h1st);

    __syncthreads();
    asm volatile("barrier.cluster.arrive.aligned;" ::: "memory");
    asm volatile("barrier.cluster.wait.aligned;" ::: "memory");

    // initial precompute for grp1: bias + Whh0 . h0_init
    float pre = 0.0f;
    if (grp == 1) {
        float d; DOT64(d, w, (const float4*)&s_h0[0][half * 64]);
        pre = bias + d;
    }

    for (int t = 0; t < T_STEPS; t++) {
        const int p = t & 1;
        const int q = p ^ 1;
        const uint32_t par_top = (uint32_t)(((t - 1) >> 1) & 1);
        const uint32_t par_h0  = (uint32_t)((t >> 1) & 1);
        const uint32_t mb_h0q  = q ? a_mbh0_1 : a_mbh0_0;
        const uint32_t mb_h1p  = p ? a_mbh1_1 : a_mbh1_0;
        const uint32_t mb_h1q  = q ? a_mbh1_1 : a_mbh1_0;

        if (grp == 1) {
            // ---- layer-0 gates: pre (done last iter) + wi*y ----
            if (t > 0) {
                mb_wait(mb_h1p, par_top);
                if (tid == 128) mb_expect(mb_h1p, H1_TX);   // re-arm for t+2
            }
            const float4* fv = (const float4*)&s_fcp[p][0];
            float4 f0 = fv[0], f1 = fv[1];
            float y = fc_b + ((f0.x + f0.y) + (f0.z + f0.w))
                           + ((f1.x + f1.y) + (f1.z + f1.w));
            if (t > 0 && rank == 0 && tid == 128) out[b * T_STEPS + (t - 1)] = y;
            float s = fmaf(wi, y, pre);
            s += __shfl_xor_sync(0xffffffffu, s, 1);
            if (!half) s_g0[row] = s;
            barn(1, 128);                                   // warps 4-7

            if (wid == 7) {                                 // layer-0 nonlin + bcast
                if (lane < SLICE) {
                    float gi = s_g0[lane],      gf = s_g0[16 + lane];
                    float gg = s_g0[32 + lane], go = s_g0[48 + lane];
                    c0r = sigf(gf) * c0r + sigf(gi) * tanh_f(gg);
                    s_h0st[lane] = sigf(go) * tanh_f(c0r);
                }
                __syncwarp();
                fence_async_proxy();   // STS visible to async proxy before bulk
                if (lane < CSZ) {      // one 64B bulk per destination = 1 tx event
                    uint32_t dst = mapa_rank(q ? a_h0d_1 : a_h0d_0, (uint32_t)lane);
                    uint32_t mbr = mapa_rank(mb_h0q, (uint32_t)lane);
                    bulk_dsmem(dst, a_h0st, 64u, mbr);
                }
            }
        } else if (grp == 0) {
            // ---- bias + Whh1 . h1[p] (consumed after syncthreads; slack) ----
            if (t > 0) mb_wait(mb_h1p, par_top);
            float d; DOT64(d, w, (const float4*)&s_h1[p][half * 64]);
            float s = bias + d;
            s += __shfl_xor_sync(0xffffffffu, s, 1);
            if (!half) s_g1a[row] = s;
        } else {
            // ---- Wih1 . h0_new (critical dot) ----
            mb_wait(mb_h0q, par_h0);
            if (tid == 256) mb_expect(mb_h0q, H0_TX);       // re-arm for t+2
            float d; DOT64(d, w, (const float4*)&s_h0[q][half * 64]);
            float s = d;
            s += __shfl_xor_sync(0xffffffffu, s, 1);
            if (!half) s_g1b[row] = s;
        }

        __syncthreads();    // converge: g1a/g1b ready; h0[q] stable for precompute

        if (grp == 1) {
            // precompute next step's Whh0 dot while warp 11 runs nonlin/exchange
            float d; DOT64(d, w, (const float4*)&s_h0[q][half * 64]);
            pre = bias + d;
        } else if (wid == 11) {                             // layer-1 nonlin + bcast
            float h1n = 0.0f;
            if (lane < SLICE) {
                float gi = s_g1a[lane]      + s_g1b[lane];
                float gf = s_g1a[16 + lane] + s_g1b[16 + lane];
                float gg = s_g1a[32 + lane] + s_g1b[32 + lane];
                float go = s_g1a[48 + lane] + s_g1b[48 + lane];
                c1r = sigf(gf) * c1r + sigf(gi) * tanh_f(gg);
                h1n = sigf(go) * tanh_f(c1r);
                s_h1st[lane] = h1n;
            }
            __syncwarp();
            fence_async_proxy();
            // h1 bulks first so the DSMEM flight overlaps the fc reduction
            if (lane < CSZ) {
                uint32_t dst = mapa_rank(q ? a_h1d_1 : a_h1d_0, (uint32_t)lane);
                uint32_t mbr = mapa_rank(mb_h1q, (uint32_t)lane);
                bulk_dsmem(dst, a_h1st, 64u, mbr);
            }
            if (lane < SLICE) {
                float fcp = fcwr * h1n;
                fcp += __shfl_xor_sync(0x0000ffffu, fcp, 8);
                fcp += __shfl_xor_sync(0x0000ffffu, fcp, 4);
                fcp += __shfl_xor_sync(0x0000ffffu, fcp, 2);
                fcp += __shfl_xor_sync(0x0000ffffu, fcp, 1);
                if (lane < CSZ) {
                    uint32_t fdst = mapa_rank(q ? a_fcd_1 : a_fcd_0, (uint32_t)lane);
                    uint32_t fmbr = mapa_rank(mb_h1q, (uint32_t)lane);
                    st_async32(fdst, __float_as_uint(fcp), fmbr);
                }
            }
        }
    }

    // final output (exchange of iter T-1 landed in buffer 0)
    if (rank == 0 && tid == 128) {
        mb_wait(a_mbh1_0, (uint32_t)(((T_STEPS - 1) >> 1) & 1));
        float y = fc_b;
        #pragma unroll
        for (int i = 0; i < CSZ; i++) y += s_fcp[0][i];
        out[b * T_STEPS + (T_STEPS - 1)] = y;
    }

    asm volatile("barrier.cluster.arrive.aligned;" ::: "memory");
    asm volatile("barrier.cluster.wait.aligned;" ::: "memory");
}

extern "C" void kernel_launch(void* const* d_in, const int* in_sizes, int n_in,
                              void* d_out, int out_size) {
    (void)in_sizes; (void)n_in; (void)out_size;
    const float* y0    = (const float*)d_in[0];
    const float* h0    = (const float*)d_in[1];
    const float* c0    = (const float*)d_in[2];
    const float* W_ih0 = (const float*)d_in[3];
    const float* W_hh0 = (const float*)d_in[4];
    const float* b_ih0 = (const float*)d_in[5];
    const float* b_hh0 = (const float*)d_in[6];
    const float* W_ih1 = (const float*)d_in[7];
    const float* W_hh1 = (const float*)d_in[8];
    const float* b_ih1 = (const float*)d_in[9];
    const float* b_hh1 = (const float*)d_in[10];
    const float* fc_w  = (const float*)d_in[11];
    const float* fc_b  = (const float*)d_in[12];
    float* out = (float*)d_out;

    lstm_decoder_kernel<<<BATCH * CSZ, NTH>>>(
        y0, h0, c0, W_ih0, W_hh0, b_ih0, b_hh0,
        W_ih1, W_hh1, b_ih1, b_hh1, fc_w, fc_b, out);
}

// round 6
// speedup vs baseline: 1.3372x; 1.3372x over previous
#include <cuda_runtime.h>
#include <cstdint>

#define T_STEPS 8640
#define HID     128
#define BATCH   16
#define CSZ     8
#define SLICE   16          /* HID / CSZ */
#define NTH     384
#define LOG2E   1.4426950408889634f
#define H0_TX   512         /* 8 src * 16 floats * 4B */
#define H1_TX   544         /* 8 src * (16 floats + 1 fc float) * 4B */

// ---------------- PTX helpers ----------------
__device__ __forceinline__ uint32_t smem_u32(const void* p) {
    return (uint32_t)__cvta_generic_to_shared(p);
}
__device__ __forceinline__ uint32_t mapa_rank(uint32_t a, uint32_t r) {
    uint32_t d;
    asm volatile("mapa.shared::cluster.u32 %0, %1, %2;" : "=r"(d) : "r"(a), "r"(r));
    return d;
}
// fused remote store + tx-arrive on the remote mbarrier; 128-bit => 1 arrival / 16B
__device__ __forceinline__ void st_async128(uint32_t a, uint4 v, uint32_t mb) {
    asm volatile(
        "st.async.shared::cluster.mbarrier::complete_tx::bytes.v4.b32 "
        "[%0], {%1,%2,%3,%4}, [%5];"
        :: "r"(a), "r"(v.x), "r"(v.y), "r"(v.z), "r"(v.w), "r"(mb) : "memory");
}
__device__ __forceinline__ void st_async32(uint32_t a, uint32_t v, uint32_t mb) {
    asm volatile("st.async.shared::cluster.mbarrier::complete_tx::bytes.b32 [%0], %1, [%2];"
                 :: "r"(a), "r"(v), "r"(mb) : "memory");
}
__device__ __forceinline__ void mb_init(uint32_t a, uint32_t n) {
    asm volatile("mbarrier.init.shared.b64 [%0], %1;" :: "r"(a), "r"(n) : "memory");
}
__device__ __forceinline__ void mb_expect(uint32_t a, uint32_t tx) {
    asm volatile("mbarrier.arrive.expect_tx.shared.b64 _, [%0], %1;"
                 :: "r"(a), "r"(tx) : "memory");
}
// cta-scope acquire wait: sufficient because data arrives via complete_tx
__device__ __forceinline__ void mb_wait(uint32_t a, uint32_t par) {
    asm volatile(
        "{\n\t"
        ".reg .pred P;\n\t"
        "WL_%=:\n\t"
        "mbarrier.try_wait.parity.acquire.cta.shared::cta.b64 P, [%0], %1, 0x989680;\n\t"
        "@P bra.uni WD_%=;\n\t"
        "bra.uni WL_%=;\n\t"
        "WD_%=:\n\t"
        "}"
        :: "r"(a), "r"(par) : "memory");
}
__device__ __forceinline__ void barn(int id, int n) {
    asm volatile("bar.sync %0, %1;" :: "r"(id), "r"(n) : "memory");
}
// fast transcendentals (~1e-6 rel err)
__device__ __forceinline__ float ex2f(float x) {
    float r; asm("ex2.approx.f32 %0, %1;" : "=f"(r) : "f"(x)); return r;
}
__device__ __forceinline__ float rcpf(float x) {
    float r; asm("rcp.approx.f32 %0, %1;" : "=f"(r) : "f"(x)); return r;
}
__device__ __forceinline__ float sigf(float x) {
    return rcpf(1.0f + ex2f(-LOG2E * x));
}
__device__ __forceinline__ float tanh_f(float x) {
    float t = ex2f(-2.0f * LOG2E * x);
    return (1.0f - t) * rcpf(1.0f + t);
}

#define DOT64(res, w, hv)                                            \
    {                                                                \
        float a0 = 0.f, a1 = 0.f, a2 = 0.f, a3 = 0.f;                \
        _Pragma("unroll")                                            \
        for (int k = 0; k < 16; k++) {                               \
            float4 v = (hv)[k];                                      \
            a0 = fmaf((w)[4 * k + 0], v.x, a0);                      \
            a1 = fmaf((w)[4 * k + 1], v.y, a1);                      \
            a2 = fmaf((w)[4 * k + 2], v.z, a2);                      \
            a3 = fmaf((w)[4 * k + 3], v.w, a3);                      \
        }                                                            \
        res = (a0 + a1) + (a2 + a3);                                 \
    }

// ---------------- kernel ----------------
// 8-CTA cluster per batch element; CTA `rank` owns hidden slice
// [16*rank, 16*rank+16) of both layers -> 64 gate rows of each matrix.
// Warp roles (hi-wid-first arbiter: critical warps get high wid):
//   warps 0-3  (grp 0): Whh1 rows (reads s_h1[p], off critical path)
//   warps 4-7  (grp 1): Whh0 rows, precomputed after syncthreads;
//                       warp 7 = layer-0 nonlin + h0 st.async128 broadcast
//   warps 8-11 (grp 2): Wih1 rows (critical dot);
//                       warp 11 = layer-1 nonlin + h1 st.async128 / fc broadcast
__global__ void __launch_bounds__(NTH, 1) __cluster_dims__(CSZ, 1, 1)
lstm_decoder_kernel(
    const float* __restrict__ y0,
    const float* __restrict__ h0in,
    const float* __restrict__ c0in,
    const float* __restrict__ wih0,
    const float* __restrict__ whh0,
    const float* __restrict__ bih0,
    const float* __restrict__ bhh0,
    const float* __restrict__ wih1,
    const float* __restrict__ whh1,
    const float* __restrict__ bih1,
    const float* __restrict__ bhh1,
    const float* __restrict__ fcw,
    const float* __restrict__ fcb,
    float* __restrict__ out)
{
    __shared__ __align__(16) float s_h0[2][HID];
    __shared__ __align__(16) float s_h1[2][HID];
    __shared__ __align__(16) float s_g0[64];     // layer-0 pre-acts (grp1)
    __shared__ __align__(16) float s_g1a[64];    // bias + Whh1*h1    (grp0)
    __shared__ __align__(16) float s_g1b[64];    // Wih1*h0_new       (grp2)
    __shared__ __align__(16) float s_h0st[SLICE];
    __shared__ __align__(16) float s_h1st[SLICE];
    __shared__ __align__(16) float s_fcp[2][CSZ];
    __shared__ __align__(8) unsigned long long s_mb_h0[2];
    __shared__ __align__(8) unsigned long long s_mb_h1[2];

    const int tid  = threadIdx.x;
    const int lane = tid & 31;
    const int wid  = tid >> 5;
    uint32_t rank;
    asm("mov.u32 %0, %%cluster_ctarank;" : "=r"(rank));
    const int b = blockIdx.x >> 3;

    const int grp  = tid >> 7;               // 0:Whh1  1:Whh0  2:Wih1
    const int half = tid & 1;
    const int row  = (tid & 127) >> 1;       // local gate row 0..63
    const int gate = row >> 4;
    const int jloc = row & 15;
    const int grow = gate * HID + (int)rank * SLICE + jloc;

    const uint32_t a_mbh0_0 = smem_u32(&s_mb_h0[0]);
    const uint32_t a_mbh0_1 = smem_u32(&s_mb_h0[1]);
    const uint32_t a_mbh1_0 = smem_u32(&s_mb_h1[0]);
    const uint32_t a_mbh1_1 = smem_u32(&s_mb_h1[1]);

    if (tid == 0) {
        mb_init(a_mbh0_0, 1);
        mb_init(a_mbh0_1, 1);
        mb_init(a_mbh1_0, 1);
        mb_init(a_mbh1_1, 1);
        mb_expect(a_mbh0_0, H0_TX);
        mb_expect(a_mbh0_1, H0_TX);
        mb_expect(a_mbh1_0, H1_TX);
        mb_expect(a_mbh1_1, H1_TX);
        s_fcp[0][0] = y0[b] - fcb[0];        // stage so iter 0 sees y = y0[b]
        #pragma unroll
        for (int i = 1; i < CSZ; i++) s_fcp[0][i] = 0.0f;
    }

    for (int k = tid; k < HID; k += NTH) {
        s_h0[0][k] = h0in[b * HID + k];
        s_h1[0][k] = h0in[BATCH * HID + b * HID + k];
    }

    // weights (register-resident, 64 per thread)
    float w[64];
    {
        const float* Wsrc = (grp == 0) ? whh1 : (grp == 1) ? whh0 : wih1;
        const float* src  = Wsrc + (size_t)grow * HID + half * 64;
        #pragma unroll
        for (int i = 0; i < 64; i++) w[i] = src[i];
    }
    float bias = 0.0f, wi = 0.0f;
    if (half == 0) {
        if (grp == 0)      { bias = bih1[grow] + bhh1[grow]; }
        else if (grp == 1) { bias = bih0[grow] + bhh0[grow]; wi = wih0[grow]; }
    }

    float c0r = 0.0f, c1r = 0.0f, fcwr = 0.0f;
    if (wid == 7 && lane < SLICE)
        c0r = c0in[b * HID + (int)rank * SLICE + lane];
    if (wid == 11 && lane < SLICE) {
        c1r  = c0in[BATCH * HID + b * HID + (int)rank * SLICE + lane];
        fcwr = fcw[(int)rank * SLICE + lane];
    }
    const float fc_b = fcb[0];

    const uint32_t a_h0d_0 = smem_u32(&s_h0[0][(int)rank * SLICE]);
    const uint32_t a_h0d_1 = smem_u32(&s_h0[1][(int)rank * SLICE]);
    const uint32_t a_h1d_0 = smem_u32(&s_h1[0][(int)rank * SLICE]);
    const uint32_t a_h1d_1 = smem_u32(&s_h1[1][(int)rank * SLICE]);
    const uint32_t a_fcd_0 = smem_u32(&s_fcp[0][rank]);
    const uint32_t a_fcd_1 = smem_u32(&s_fcp[1][rank]);

    __syncthreads();
    asm volatile("barrier.cluster.arrive.aligned;" ::: "memory");
    asm volatile("barrier.cluster.wait.aligned;" ::: "memory");

    // initial precompute for grp1: bias + Whh0 . h0_init
    float pre = 0.0f;
    if (grp == 1) {
        float d; DOT64(d, w, (const float4*)&s_h0[0][half * 64]);
        pre = bias + d;
    }

    for (int t = 0; t < T_STEPS; t++) {
        const int p = t & 1;
        const int q = p ^ 1;
        const uint32_t par_top = (uint32_t)(((t - 1) >> 1) & 1);
        const uint32_t par_h0  = (uint32_t)((t >> 1) & 1);
        const uint32_t mb_h0q  = q ? a_mbh0_1 : a_mbh0_0;
        const uint32_t mb_h1p  = p ? a_mbh1_1 : a_mbh1_0;
        const uint32_t mb_h1q  = q ? a_mbh1_1 : a_mbh1_0;

        if (grp == 1) {
            // ---- layer-0 gates: pre (done last iter) + wi*y ----
            if (t > 0) {
                mb_wait(mb_h1p, par_top);
                if (tid == 128) mb_expect(mb_h1p, H1_TX);   // re-arm for t+2
            }
            const float4* fv = (const float4*)&s_fcp[p][0];
            float4 f0 = fv[0], f1 = fv[1];
            float y = fc_b + ((f0.x + f0.y) + (f0.z + f0.w))
                           + ((f1.x + f1.y) + (f1.z + f1.w));
            if (t > 0 && rank == 0 && tid == 128) out[b * T_STEPS + (t - 1)] = y;
            float s = fmaf(wi, y, pre);
            s += __shfl_xor_sync(0xffffffffu, s, 1);
            if (!half) s_g0[row] = s;
            barn(1, 128);                                   // warps 4-7

            if (wid == 7) {                                 // layer-0 nonlin + bcast
                if (lane < SLICE) {
                    float gi = s_g0[lane],      gf = s_g0[16 + lane];
                    float gg = s_g0[32 + lane], go = s_g0[48 + lane];
                    c0r = sigf(gf) * c0r + sigf(gi) * tanh_f(gg);
                    s_h0st[lane] = sigf(go) * tanh_f(c0r);
                }
                __syncwarp();
                // 32 lanes: 8 dests x 4 16B-quarters; dest staggered by rank
                const int dest = ((lane >> 2) + (int)rank) & 7;
                const int qtr  = lane & 3;
                uint32_t dst = mapa_rank((q ? a_h0d_1 : a_h0d_0) + 16u * qtr,
                                         (uint32_t)dest);
                uint32_t mbr = mapa_rank(mb_h0q, (uint32_t)dest);
                uint4 v = ((const uint4*)s_h0st)[qtr];
                st_async128(dst, v, mbr);
            }
        } else if (grp == 0) {
            // ---- bias + Whh1 . h1[p] (consumed after syncthreads; slack) ----
            if (t > 0) mb_wait(mb_h1p, par_top);
            float d; DOT64(d, w, (const float4*)&s_h1[p][half * 64]);
            float s = bias + d;
            s += __shfl_xor_sync(0xffffffffu, s, 1);
            if (!half) s_g1a[row] = s;
        } else {
            // ---- Wih1 . h0_new (critical dot) ----
            mb_wait(mb_h0q, par_h0);
            if (tid == 256) mb_expect(mb_h0q, H0_TX);       // re-arm for t+2
            float d; DOT64(d, w, (const float4*)&s_h0[q][half * 64]);
            float s = d;
            s += __shfl_xor_sync(0xffffffffu, s, 1);
            if (!half) s_g1b[row] = s;
        }

        __syncthreads();    // converge: g1a/g1b ready; h0[q] stable for precompute

        if (grp == 1) {
            // precompute next step's Whh0 dot while warp 11 runs nonlin/exchange
            float d; DOT64(d, w, (const float4*)&s_h0[q][half * 64]);
            pre = bias + d;
        } else if (wid == 11) {                             // layer-1 nonlin + bcast
            float h1n = 0.0f;
            if (lane < SLICE) {
                float gi = s_g1a[lane]      + s_g1b[lane];
                float gf = s_g1a[16 + lane] + s_g1b[16 + lane];
                float gg = s_g1a[32 + lane] + s_g1b[32 + lane];
                float go = s_g1a[48 + lane] + s_g1b[48 + lane];
                c1r = sigf(gf) * c1r + sigf(gi) * tanh_f(gg);
                h1n = sigf(go) * tanh_f(c1r);
                s_h1st[lane] = h1n;
            }
            __syncwarp();
            // h1 stores first so DSMEM flight overlaps the fc reduction
            {
                const int dest = ((lane >> 2) + (int)rank) & 7;
                const int qtr  = lane & 3;
                uint32_t dst = mapa_rank((q ? a_h1d_1 : a_h1d_0) + 16u * qtr,
                                         (uint32_t)dest);
                uint32_t mbr = mapa_rank(mb_h1q, (uint32_t)dest);
                uint4 v = ((const uint4*)s_h1st)[qtr];
                st_async128(dst, v, mbr);
            }
            if (lane < SLICE) {
                float fcp = fcwr * h1n;
                fcp += __shfl_xor_sync(0x0000ffffu, fcp, 8);
                fcp += __shfl_xor_sync(0x0000ffffu, fcp, 4);
                fcp += __shfl_xor_sync(0x0000ffffu, fcp, 2);
                fcp += __shfl_xor_sync(0x0000ffffu, fcp, 1);
                if (lane < CSZ) {
                    const int fdest = (lane + (int)rank) & 7;
                    uint32_t fdst = mapa_rank(q ? a_fcd_1 : a_fcd_0, (uint32_t)fdest);
                    uint32_t fmbr = mapa_rank(mb_h1q, (uint32_t)fdest);
                    st_async32(fdst, __float_as_uint(fcp), fmbr);
                }
            }
        }
    }

    // final output (exchange of iter T-1 landed in buffer 0)
    if (rank == 0 && tid == 128) {
        mb_wait(a_mbh1_0, (uint32_t)(((T_STEPS - 1) >> 1) & 1));
        float y = fc_b;
        #pragma unroll
        for (int i = 0; i < CSZ; i++) y += s_fcp[0][i];
        out[b * T_STEPS + (T_STEPS - 1)] = y;
    }

    asm volatile("barrier.cluster.arrive.aligned;" ::: "memory");
    asm volatile("barrier.cluster.wait.aligned;" ::: "memory");
}

extern "C" void kernel_launch(void* const* d_in, const int* in_sizes, int n_in,
                              void* d_out, int out_size) {
    (void)in_sizes; (void)n_in; (void)out_size;
    const float* y0    = (const float*)d_in[0];
    const float* h0    = (const float*)d_in[1];
    const float* c0    = (const float*)d_in[2];
    const float* W_ih0 = (const float*)d_in[3];
    const float* W_hh0 = (const float*)d_in[4];
    const float* b_ih0 = (const float*)d_in[5];
    const float* b_hh0 = (const float*)d_in[6];
    const float* W_ih1 = (const float*)d_in[7];
    const float* W_hh1 = (const float*)d_in[8];
    const float* b_ih1 = (const float*)d_in[9];
    const float* b_hh1 = (const float*)d_in[10];
    const float* fc_w  = (const float*)d_in[11];
    const float* fc_b  = (const float*)d_in[12];
    float* out = (float*)d_out;

    lstm_decoder_kernel<<<BATCH * CSZ, NTH>>>(
        y0, h0, c0, W_ih0, W_hh0, b_ih0, b_hh0,
        W_ih1, W_hh1, b_ih1, b_hh1, fc_w, fc_b, out);
}